// round 7
// baseline (speedup 1.0000x reference)
#include <cuda_runtime.h>

// Problem constants (fixed shapes from reference):
//   outputs1/2, input1/2 : [64,3,256,256] f32  -> NEL = 12,582,912 each
//   z1/z2                : [64,64,16,16]  f32  -> [64, 16384] flattened
#define BZ 64
#define DZ 16384
#define NEL 12582912
#define N4 (NEL / 4)

#define NGEMM_BLOCKS 128        // each owns a 128-wide k-slice of the cross GEMM
#define SLICE 128
#define NMSE_BLOCKS 1024        // 1024 * 256 * 12 == N4 exactly; <=1184 resident -> one wave
#define MSE_ITERS 12

// Deterministic scratch (no atomics on data, every slot rewritten every launch)
__device__ float  g_crossp[NGEMM_BLOCKS * 64 * 64]; // per-block partial cross[m][n]
__device__ float  g_sqp[128 * NGEMM_BLOCKS];        // per-entry-per-block sq partials, [entry][block]
__device__ double g_msep[NMSE_BLOCKS];              // per-block MSE partial sums
__device__ double g_mse_total;                      // fully reduced MSE sum
__device__ double g_row_lp[64];                     // per-row positive-margin term
__device__ double g_row_ln[64];                     // per-row negative-margin sum

// ---------------------------------------------------------------------------
// Kernel 1: cross-matrix partials + sum-of-squares partials (from the same data)
// Block b owns D slice [b*128, b*128+128). Full register budget.
// ---------------------------------------------------------------------------
__global__ __launch_bounds__(256)
void gemm_kernel(const float* __restrict__ z1, const float* __restrict__ z2)
{
    const int tid = threadIdx.x;
    const int b   = blockIdx.x;

    // Shared tiles stored k-major: s[k][row], row padded to 68 (68*4 = 272 = 17*16,
    // so &s[k][4*t] stays 16B aligned for LDS.128 on the compute side).
    __shared__ __align__(16) float s1[32][68];
    __shared__ __align__(16) float s2[32][68];

    float acc[4][4];
#pragma unroll
    for (int i = 0; i < 4; ++i)
#pragma unroll
        for (int j = 0; j < 4; ++j) acc[i][j] = 0.0f;

    // sq partials: [0]=z1 row r0, [1]=z1 row r0+32, [2]=z2 row r0, [3]=z2 row r0+32
    float sqa[4] = {0.0f, 0.0f, 0.0f, 0.0f};

    const int tx = tid & 15;   // n-tile coordinate
    const int ty = tid >> 4;   // m-tile coordinate
    const int c0 = b * SLICE;

    for (int t = 0; t < 4; ++t) {          // 4 k-tiles of 32
        const int ck = c0 + t * 32;
        __syncthreads();
        // load 64 rows x 32 k each tensor: 512 float4 per tensor, 2 per thread
#pragma unroll
        for (int i = 0; i < 2; ++i) {
            const int idx = tid + i * 256;      // 0..511
            const int r   = idx >> 3;           // row 0..63
            const int kk  = (idx & 7) * 4;      // k within tile
            float4 v1 = *(const float4*)(z1 + r * DZ + ck + kk);
            float4 v2 = *(const float4*)(z2 + r * DZ + ck + kk);
            s1[kk + 0][r] = v1.x; s1[kk + 1][r] = v1.y;
            s1[kk + 2][r] = v1.z; s1[kk + 3][r] = v1.w;
            s2[kk + 0][r] = v2.x; s2[kk + 1][r] = v2.y;
            s2[kk + 2][r] = v2.z; s2[kk + 3][r] = v2.w;
            sqa[i]     += v1.x * v1.x + v1.y * v1.y + v1.z * v1.z + v1.w * v1.w;
            sqa[2 + i] += v2.x * v2.x + v2.y * v2.y + v2.z * v2.z + v2.w * v2.w;
        }
        __syncthreads();
#pragma unroll
        for (int k = 0; k < 32; ++k) {
            const float4 av = *(const float4*)&s1[k][ty * 4];
            const float4 bv = *(const float4*)&s2[k][tx * 4];
            const float a[4] = {av.x, av.y, av.z, av.w};
            const float c[4] = {bv.x, bv.y, bv.z, bv.w};
#pragma unroll
            for (int i = 0; i < 4; ++i)
#pragma unroll
                for (int j = 0; j < 4; ++j) acc[i][j] += a[i] * c[j];
        }
    }

    float* outp = g_crossp + b * 4096;
#pragma unroll
    for (int i = 0; i < 4; ++i)
#pragma unroll
        for (int j = 0; j < 4; ++j)
            outp[(ty * 4 + i) * 64 + (tx * 4 + j)] = acc[i][j];

    // reduce sq partials over the 8 threads sharing one row (consecutive tids)
#pragma unroll
    for (int j = 0; j < 4; ++j) {
        float v = sqa[j];
        v += __shfl_down_sync(0xffffffffu, v, 4);
        v += __shfl_down_sync(0xffffffffu, v, 2);
        v += __shfl_down_sync(0xffffffffu, v, 1);
        sqa[j] = v;
    }
    if ((tid & 7) == 0) {
        const int r0 = tid >> 3;            // 0..31
        g_sqp[(r0)          * NGEMM_BLOCKS + b] = sqa[0];   // z1 row r0
        g_sqp[(r0 + 32)     * NGEMM_BLOCKS + b] = sqa[1];   // z1 row r0+32
        g_sqp[(64 + r0)     * NGEMM_BLOCKS + b] = sqa[2];   // z2 row r0
        g_sqp[(64 + r0 + 32)* NGEMM_BLOCKS + b] = sqa[3];   // z2 row r0+32
    }
}

// ---------------------------------------------------------------------------
// Kernel 2: pure MSE streaming reduction. <=32 regs -> 8 CTAs/SM, 64 warps.
// Block b owns float4 chunk [b*3072, (b+1)*3072).
// ---------------------------------------------------------------------------
__global__ __launch_bounds__(256, 8)
void mse_kernel(const float* __restrict__ o1, const float* __restrict__ i1,
                const float* __restrict__ o2, const float* __restrict__ i2)
{
    const int tid  = threadIdx.x;
    const int base = blockIdx.x * (MSE_ITERS * 256) + tid;
    const float4* a1 = (const float4*)o1;
    const float4* c1 = (const float4*)i1;
    const float4* a2 = (const float4*)o2;
    const float4* c2 = (const float4*)i2;

    float sum = 0.0f;
#pragma unroll
    for (int it = 0; it < MSE_ITERS; ++it) {
        const int idx = base + it * 256;
        const float4 x1 = __ldcs(a1 + idx);
        const float4 y1 = __ldcs(c1 + idx);
        const float4 x2 = __ldcs(a2 + idx);
        const float4 y2 = __ldcs(c2 + idx);
        float dx = x1.x - y1.x, dy = x1.y - y1.y, dz = x1.z - y1.z, dw = x1.w - y1.w;
        sum += dx * dx + dy * dy + dz * dz + dw * dw;
        dx = x2.x - y2.x; dy = x2.y - y2.y; dz = x2.z - y2.z; dw = x2.w - y2.w;
        sum += dx * dx + dy * dy + dz * dz + dw * dw;
    }

    __shared__ float red[8];
#pragma unroll
    for (int off = 16; off; off >>= 1) sum += __shfl_down_sync(0xffffffffu, sum, off);
    if ((tid & 31) == 0) red[tid >> 5] = sum;
    __syncthreads();
    if (tid < 32) {
        float v = (tid < 8) ? red[tid] : 0.0f;
#pragma unroll
        for (int off = 4; off; off >>= 1) v += __shfl_down_sync(0xffffffffu, v, off);
        if (tid == 0) g_msep[blockIdx.x] = (double)v;
    }
}

// ---------------------------------------------------------------------------
// Kernel 3: blocks 0..63 reduce sq + cross row m + margins; block 64 reduces MSE.
// ---------------------------------------------------------------------------
__global__ __launch_bounds__(256)
void rowreduce_kernel()
{
    const int tid = threadIdx.x;

    if (blockIdx.x == 64) {
        __shared__ double mred[8];
        double msum = 0.0;
#pragma unroll
        for (int i = tid; i < NMSE_BLOCKS; i += 256) msum += g_msep[i];
#pragma unroll
        for (int o = 16; o; o >>= 1) msum += __shfl_down_sync(0xffffffffu, msum, o);
        if ((tid & 31) == 0) mred[tid >> 5] = msum;
        __syncthreads();
        if (tid == 0) {
            double t = 0.0;
#pragma unroll
            for (int i = 0; i < 8; ++i) t += mred[i];
            g_mse_total = t;
        }
        return;
    }

    const int m = blockIdx.x;
    __shared__ float sq_sm[128];

    // reduce sq partials: entry e = tid>>1 over its 128 per-block partials (contiguous)
    {
        const int e = tid >> 1, h = tid & 1;
        const float4* p = (const float4*)g_sqp;
        float s = 0.0f;
#pragma unroll
        for (int j = 0; j < 16; ++j) {
            const float4 v = p[e * 32 + h * 16 + j];
            s += v.x + v.y + v.z + v.w;
        }
        s += __shfl_xor_sync(0xffffffffu, s, 1);
        if (h == 0) sq_sm[e] = s;
    }
    __syncthreads();

    // reduce cross row m over 128 partials
    const int n = tid & 63;       // output column
    const int q = tid >> 6;       // partial group 0..3 (32 partials each)
    float s = 0.0f;
#pragma unroll
    for (int j = 0; j < 32; ++j)
        s += g_crossp[(q * 32 + j) * 4096 + m * 64 + n];

    __shared__ float sm[4][64];
    __shared__ double dred[2];
    sm[q][n] = s;
    __syncthreads();

    if (tid < 64) {
        const float cr = sm[0][tid] + sm[1][tid] + sm[2][tid] + sm[3][tid];
        const double d = ((double)sq_sm[m] + (double)sq_sm[64 + tid] - 2.0 * (double)cr)
                         * (1.0 / (double)DZ);
        double lp = 0.0, ln = 0.0;
        if (m == tid) {
            if (d > 0.01) lp = d - 0.01;
        } else if (d < 0.4) {
            ln = 0.4 - d;
        }
#pragma unroll
        for (int o = 16; o; o >>= 1) {
            lp += __shfl_down_sync(0xffffffffu, lp, o);
            ln += __shfl_down_sync(0xffffffffu, ln, o);
        }
        if ((tid & 31) == 0) dred[tid >> 5] = ln + lp;   // lp folded in (only one warp has it)
        __syncthreads();
        if (tid == 0) {
            // separate lp exactly: recompute diagonal term directly (cheap, deterministic)
            const double dd = ((double)sq_sm[m] + (double)sq_sm[64 + m]
                               - 2.0 * (double)(sm[0][m] + sm[1][m] + sm[2][m] + sm[3][m]))
                              * (1.0 / (double)DZ);
            const double lpv = (dd > 0.01) ? (dd - 0.01) : 0.0;
            g_row_lp[m] = lpv;
            g_row_ln[m] = dred[0] + dred[1] - lpv;
        }
    }
}

__device__ __forceinline__ double warp_red_d(double v)
{
#pragma unroll
    for (int o = 16; o; o >>= 1) v += __shfl_down_sync(0xffffffffu, v, o);
    return v;
}

__global__ __launch_bounds__(64)
void finalize_kernel(float* __restrict__ out)
{
    const int tid = threadIdx.x;
    __shared__ double sred[2][2];

    const double lp = g_row_lp[tid];
    const double ln = g_row_ln[tid];
    const double r1 = warp_red_d(lp);
    const double r2 = warp_red_d(ln);
    if ((tid & 31) == 0) { sred[0][tid >> 5] = r1; sred[1][tid >> 5] = r2; }
    __syncthreads();
    if (tid == 0) {
        const double recon = g_mse_total / (double)NEL;            // mean1 + mean2 combined
        const double lossP = 1.5 * ((sred[0][0] + sred[0][1]) / (double)BZ);
        const double lossN = 0.5 * ((sred[1][0] + sred[1][1]) / (double)(BZ * (BZ - 1)));
        out[0] = (float)(recon + lossP + lossN);
    }
}

extern "C" void kernel_launch(void* const* d_in, const int* in_sizes, int n_in,
                              void* d_out, int out_size)
{
    const float* o1 = (const float*)d_in[0];
    const float* z1 = (const float*)d_in[1];
    const float* o2 = (const float*)d_in[2];
    const float* z2 = (const float*)d_in[3];
    const float* i1 = (const float*)d_in[4];
    const float* i2 = (const float*)d_in[5];

    gemm_kernel<<<NGEMM_BLOCKS, 256>>>(z1, z2);
    mse_kernel<<<NMSE_BLOCKS, 256>>>(o1, i1, o2, i2);
    rowreduce_kernel<<<65, 256>>>();
    finalize_kernel<<<1, 64>>>((float*)d_out);
}

// round 8
// speedup vs baseline: 1.1420x; 1.1420x over previous
#include <cuda_runtime.h>

// Problem constants (fixed shapes from reference):
//   outputs1/2, input1/2 : [64,3,256,256] f32  -> NEL = 12,582,912 each
//   z1/z2                : [64,64,16,16]  f32  -> [64, 16384] flattened
#define BZ 64
#define DZ 16384
#define NEL 12582912
#define N4 (NEL / 4)
#define N4_HALF (N4 / 2)

#define NCTR_BLOCKS 64          // contrastive blocks, each owns a 256-wide D slice
#define NMSE_BLOCKS 676         // 64 + 676 = 740 = 5 CTAs/SM * 148 SMs -> exactly one wave
#define TOTAL_BLOCKS (NCTR_BLOCKS + NMSE_BLOCKS)

// Deterministic scratch (no atomics, every slot rewritten every launch)
__device__ float  g_crossp[NCTR_BLOCKS * 64 * 64];  // per-block partial cross[m][n]
__device__ float  g_sqp[128 * NCTR_BLOCKS];         // per-entry-per-block sq partials, [entry][block]
__device__ double g_msep[NMSE_BLOCKS];              // per-block MSE partial sums
__device__ double g_mse_total;                      // fully reduced MSE sum
__device__ double g_row_lp[64];                     // per-row positive-margin term
__device__ double g_row_ln[64];                     // per-row negative-margin sum

__global__ __launch_bounds__(256, 5)
void fused_kernel(const float* __restrict__ o1, const float* __restrict__ z1,
                  const float* __restrict__ o2, const float* __restrict__ z2,
                  const float* __restrict__ i1, const float* __restrict__ i2)
{
    const int tid = threadIdx.x;
    const int b   = blockIdx.x;

    if (b < NCTR_BLOCKS) {
        // ---------- contrastive cross-matrix partial: D slice [b*256, b*256+256) ----------
        // Shared tiles stored k-major: s[k][row], row padded to 68 (68*4 = 272 = 17*16,
        // so &s[k][4*t] stays 16B aligned for LDS.128 on the compute side).
        __shared__ __align__(16) float s1[32][68];
        __shared__ __align__(16) float s2[32][68];

        float acc[4][4];
#pragma unroll
        for (int i = 0; i < 4; ++i)
#pragma unroll
            for (int j = 0; j < 4; ++j) acc[i][j] = 0.0f;

        // sq partials computed from the same tile-load data (no extra reads):
        // [0]=z1 row (tid>>3), [1]=z1 row (tid>>3)+32, [2]/[3] same for z2
        float sqa[4] = {0.0f, 0.0f, 0.0f, 0.0f};

        const int tx = tid & 15;   // n-tile coordinate
        const int ty = tid >> 4;   // m-tile coordinate
        const int c0 = b * 256;

        for (int t = 0; t < 8; ++t) {          // 8 k-tiles of 32
            const int ck = c0 + t * 32;
            __syncthreads();
            // load 64 rows x 32 k each tensor: 512 float4 per tensor, 2 per thread
#pragma unroll
            for (int i = 0; i < 2; ++i) {
                const int idx = tid + i * 256;      // 0..511
                const int r   = idx >> 3;           // row 0..63
                const int kk  = (idx & 7) * 4;      // k within tile
                float4 v1 = *(const float4*)(z1 + r * DZ + ck + kk);
                float4 v2 = *(const float4*)(z2 + r * DZ + ck + kk);
                s1[kk + 0][r] = v1.x; s1[kk + 1][r] = v1.y;
                s1[kk + 2][r] = v1.z; s1[kk + 3][r] = v1.w;
                s2[kk + 0][r] = v2.x; s2[kk + 1][r] = v2.y;
                s2[kk + 2][r] = v2.z; s2[kk + 3][r] = v2.w;
                sqa[i]     += v1.x * v1.x + v1.y * v1.y + v1.z * v1.z + v1.w * v1.w;
                sqa[2 + i] += v2.x * v2.x + v2.y * v2.y + v2.z * v2.z + v2.w * v2.w;
            }
            __syncthreads();
#pragma unroll
            for (int k = 0; k < 32; ++k) {
                const float4 av = *(const float4*)&s1[k][ty * 4];
                const float4 bv = *(const float4*)&s2[k][tx * 4];
                const float a[4] = {av.x, av.y, av.z, av.w};
                const float c[4] = {bv.x, bv.y, bv.z, bv.w};
#pragma unroll
                for (int i = 0; i < 4; ++i)
#pragma unroll
                    for (int j = 0; j < 4; ++j) acc[i][j] += a[i] * c[j];
            }
        }

        float* outp = g_crossp + b * 4096;
#pragma unroll
        for (int i = 0; i < 4; ++i)
#pragma unroll
            for (int j = 0; j < 4; ++j)
                outp[(ty * 4 + i) * 64 + (tx * 4 + j)] = acc[i][j];

        // reduce sq partials over the 8 consecutive threads sharing one row
#pragma unroll
        for (int j = 0; j < 4; ++j) {
            float v = sqa[j];
            v += __shfl_down_sync(0xffffffffu, v, 4);
            v += __shfl_down_sync(0xffffffffu, v, 2);
            v += __shfl_down_sync(0xffffffffu, v, 1);
            sqa[j] = v;
        }
        if ((tid & 7) == 0) {
            const int r0 = tid >> 3;            // 0..31
            g_sqp[(r0)           * NCTR_BLOCKS + b] = sqa[0];   // z1 row r0
            g_sqp[(r0 + 32)      * NCTR_BLOCKS + b] = sqa[1];   // z1 row r0+32
            g_sqp[(64 + r0)      * NCTR_BLOCKS + b] = sqa[2];   // z2 row r0
            g_sqp[(64 + r0 + 32) * NCTR_BLOCKS + b] = sqa[3];   // z2 row r0+32
        }
    } else {
        // ---------- MSE: grid-stride float4; pair 2 staggered by N4/2 (mod N4) ----------
        const int mb = b - NCTR_BLOCKS;
        const float4* a1 = (const float4*)o1;
        const float4* c1 = (const float4*)i1;
        const float4* a2 = (const float4*)o2;
        const float4* c2 = (const float4*)i2;
        float sum = 0.0f;
        for (int idx = mb * 256 + tid; idx < N4; idx += NMSE_BLOCKS * 256) {
            float4 x = __ldcs(a1 + idx), y = __ldcs(c1 + idx);
            float dx = x.x - y.x, dy = x.y - y.y, dz = x.z - y.z, dw = x.w - y.w;
            sum += dx * dx + dy * dy + dz * dz + dw * dw;
            const int idx2 = (idx < N4_HALF) ? (idx + N4_HALF) : (idx - N4_HALF);
            x = __ldcs(a2 + idx2); y = __ldcs(c2 + idx2);
            dx = x.x - y.x; dy = x.y - y.y; dz = x.z - y.z; dw = x.w - y.w;
            sum += dx * dx + dy * dy + dz * dz + dw * dw;
        }
        __shared__ float red[8];
#pragma unroll
        for (int off = 16; off; off >>= 1) sum += __shfl_down_sync(0xffffffffu, sum, off);
        if ((tid & 31) == 0) red[tid >> 5] = sum;
        __syncthreads();
        if (tid < 32) {
            float v = (tid < 8) ? red[tid] : 0.0f;
#pragma unroll
            for (int off = 4; off; off >>= 1) v += __shfl_down_sync(0xffffffffu, v, off);
            if (tid == 0) g_msep[mb] = (double)v;
        }
    }
}

// Blocks 0..63: reduce sq partials + cross row m + margins. Block 64: reduce MSE partials.
__global__ __launch_bounds__(256)
void rowreduce_kernel()
{
    const int tid = threadIdx.x;

    if (blockIdx.x == 64) {
        __shared__ double mred[8];
        double msum = 0.0;
#pragma unroll
        for (int i = tid; i < NMSE_BLOCKS; i += 256) msum += g_msep[i];
#pragma unroll
        for (int o = 16; o; o >>= 1) msum += __shfl_down_sync(0xffffffffu, msum, o);
        if ((tid & 31) == 0) mred[tid >> 5] = msum;
        __syncthreads();
        if (tid == 0) {
            double t = 0.0;
#pragma unroll
            for (int i = 0; i < 8; ++i) t += mred[i];
            g_mse_total = t;
        }
        return;
    }

    const int m = blockIdx.x;
    __shared__ float sq_sm[128];

    // reduce sq partials: entry e = tid>>1 over its 64 per-block partials (contiguous)
    {
        const int e = tid >> 1, h = tid & 1;
        const float4* p = (const float4*)g_sqp;
        float s = 0.0f;
#pragma unroll
        for (int j = 0; j < 8; ++j) {
            const float4 v = p[e * 16 + h * 8 + j];
            s += v.x + v.y + v.z + v.w;
        }
        s += __shfl_xor_sync(0xffffffffu, s, 1);
        if (h == 0) sq_sm[e] = s;
    }
    __syncthreads();

    // reduce cross row m over the 64 partials
    const int n = tid & 63;       // output column
    const int q = tid >> 6;       // partial group 0..3 (16 partials each)
    float s = 0.0f;
#pragma unroll
    for (int j = 0; j < 16; ++j)
        s += g_crossp[(q * 16 + j) * 4096 + m * 64 + n];

    __shared__ float sm[4][64];
    __shared__ double dred[2];
    sm[q][n] = s;
    __syncthreads();

    if (tid < 64) {
        const float cr = sm[0][tid] + sm[1][tid] + sm[2][tid] + sm[3][tid];
        const double d = ((double)sq_sm[m] + (double)sq_sm[64 + tid] - 2.0 * (double)cr)
                         * (1.0 / (double)DZ);
        double lp = 0.0, ln = 0.0;
        if (m == tid) {
            if (d > 0.01) lp = d - 0.01;
        } else if (d < 0.4) {
            ln = 0.4 - d;
        }
#pragma unroll
        for (int o = 16; o; o >>= 1) {
            lp += __shfl_down_sync(0xffffffffu, lp, o);
            ln += __shfl_down_sync(0xffffffffu, ln, o);
        }
        if ((tid & 31) == 0) dred[tid >> 5] = ln + lp;   // lp folded in (only one warp has it)
        __syncthreads();
        if (tid == 0) {
            // separate lp exactly: recompute diagonal term directly (cheap, deterministic)
            const double dd = ((double)sq_sm[m] + (double)sq_sm[64 + m]
                               - 2.0 * (double)(sm[0][m] + sm[1][m] + sm[2][m] + sm[3][m]))
                              * (1.0 / (double)DZ);
            const double lpv = (dd > 0.01) ? (dd - 0.01) : 0.0;
            g_row_lp[m] = lpv;
            g_row_ln[m] = dred[0] + dred[1] - lpv;
        }
    }
}

__device__ __forceinline__ double warp_red_d(double v)
{
#pragma unroll
    for (int o = 16; o; o >>= 1) v += __shfl_down_sync(0xffffffffu, v, o);
    return v;
}

__global__ __launch_bounds__(64)
void finalize_kernel(float* __restrict__ out)
{
    const int tid = threadIdx.x;
    __shared__ double sred[2][2];

    const double lp = g_row_lp[tid];
    const double ln = g_row_ln[tid];
    const double r1 = warp_red_d(lp);
    const double r2 = warp_red_d(ln);
    if ((tid & 31) == 0) { sred[0][tid >> 5] = r1; sred[1][tid >> 5] = r2; }
    __syncthreads();
    if (tid == 0) {
        const double recon = g_mse_total / (double)NEL;            // mean1 + mean2 combined
        const double lossP = 1.5 * ((sred[0][0] + sred[0][1]) / (double)BZ);
        const double lossN = 0.5 * ((sred[1][0] + sred[1][1]) / (double)(BZ * (BZ - 1)));
        out[0] = (float)(recon + lossP + lossN);
    }
}

extern "C" void kernel_launch(void* const* d_in, const int* in_sizes, int n_in,
                              void* d_out, int out_size)
{
    const float* o1 = (const float*)d_in[0];
    const float* z1 = (const float*)d_in[1];
    const float* o2 = (const float*)d_in[2];
    const float* z2 = (const float*)d_in[3];
    const float* i1 = (const float*)d_in[4];
    const float* i2 = (const float*)d_in[5];

    fused_kernel<<<TOTAL_BLOCKS, 256>>>(o1, z1, o2, z2, i1, i2);
    rowreduce_kernel<<<65, 256>>>();
    finalize_kernel<<<1, 64>>>((float*)d_out);
}